// round 5
// baseline (speedup 1.0000x reference)
#include <cuda_runtime.h>
#include <math_constants.h>
#include <cstdint>

#define DD 128
#define BQ 32
#define KTOP 16
#define TILE_R 128
#define THREADS 64
#define NCTA 296
#define SCST 34            // score buffer stride (floats)

// shared layout (floats) for k_main
#define OFF_A   0
#define OFF_Q   (OFF_A + TILE_R*DD)        // 16384
#define OFF_SC  (OFF_Q + DD*BQ)            // 20480
#define OFF_CB  (OFF_SC + TILE_R*SCST)     // 24832
#define SMEM_FLOATS (OFF_CB + BQ)
#define SMEM_BYTES  (SMEM_FLOATS*4)        // 99456 B

__device__ float g_q[BQ*DD];
__device__ float g_qn[BQ];
__device__ float g_cb[BQ];
__device__ float g_cand_s[NCTA*BQ*KTOP];
__device__ int   g_cand_i[NCTA*BQ*KTOP];
__device__ float g_minred[NCTA*BQ];

// ---- packed f32x2 helpers (sm_103a) ----
__device__ __forceinline__ unsigned long long dup2(float a) {
    unsigned long long d;
    asm("mov.b64 %0, {%1, %1};" : "=l"(d) : "f"(a));
    return d;
}
__device__ __forceinline__ void fma2(unsigned long long& d,
                                     unsigned long long a,
                                     unsigned long long b) {
    asm("fma.rn.f32x2 %0, %1, %2, %0;" : "+l"(d) : "l"(a), "l"(b));
}
__device__ __forceinline__ void unpack2(unsigned long long v, float& lo, float& hi) {
    asm("mov.b64 {%0, %1}, %2;" : "=f"(lo), "=f"(hi) : "l"(v));
}
__device__ __forceinline__ float rsqrt_nr(float x) {
    float r;
    asm("rsqrt.approx.f32 %0, %1;" : "=f"(r) : "f"(x));
    float h = 0.5f * x;
    r = r * fmaf(-h * r, r, 1.5f);
    return r;
}

// ---------------------------------------------------------------------------
// Kernel 1: q = query @ Wq^T + bq ; ||q|| ; 0.7/||q||
// ---------------------------------------------------------------------------
__global__ void k_setup(const float* __restrict__ query,
                        const float* __restrict__ Wq,
                        const float* __restrict__ bqv) {
    __shared__ float sq[DD];
    __shared__ float red[DD];
    int b = blockIdx.x;
    int j = threadIdx.x;
    sq[j] = query[b*DD + j];
    __syncthreads();
    const float* wr = Wq + (size_t)j * DD;
    float a0 = 0.f, a1 = 0.f, a2 = 0.f, a3 = 0.f;
    #pragma unroll 8
    for (int d = 0; d < DD; d += 4) {
        a0 = fmaf(sq[d+0], wr[d+0], a0);
        a1 = fmaf(sq[d+1], wr[d+1], a1);
        a2 = fmaf(sq[d+2], wr[d+2], a2);
        a3 = fmaf(sq[d+3], wr[d+3], a3);
    }
    float v = ((a0 + a1) + (a2 + a3)) + bqv[j];
    g_q[b*DD + j] = v;
    red[j] = v * v;
    __syncthreads();
    for (int s = 64; s > 0; s >>= 1) {
        if (j < s) red[j] += red[j + s];
        __syncthreads();
    }
    if (j == 0) {
        float qn = sqrtf(red[0]);
        g_qn[b] = qn;
        g_cb[b] = 0.7f / qn;
    }
}

// ---------------------------------------------------------------------------
// Kernel 2: 8x8 register-tiled FFMA2 dots + fused norms + top-16 + min-d2
// ---------------------------------------------------------------------------
__global__ void __launch_bounds__(THREADS, 2)
k_main(const float* __restrict__ mem, const float* __restrict__ imp,
       const int* __restrict__ ts, const int* __restrict__ ctp,
       int N, int tpc) {
    extern __shared__ float smf[];
    float* sA  = smf + OFF_A;
    float* sQ  = smf + OFF_Q;
    float* sSC = smf + OFF_SC;
    float* sCB = smf + OFF_CB;

    const int t   = threadIdx.x;
    const int cta = blockIdx.x;
    const int qg  = t & 3;           // 8 queries
    const int rg  = t >> 2;          // 8 rows, rg in [0,16)
    const int b0  = qg * 8;
    const int r0  = rg * 8;
    const int sw  = rg & 7;          // per-row-group swizzle (matches (row>>3)&7)

    // stage q transposed: sQ[k*32 + b]
    for (int o = t; o < BQ*DD; o += THREADS) {
        int b = o >> 7, k = o & 127;
        sQ[k*BQ + b] = g_q[o];
    }
    if (t < BQ) sCB[t] = g_cb[t];

    const float inv_ct1 = 1.0f / ((float)(*ctp) + 1.0f);

    float lmn[8];
    #pragma unroll
    for (int j = 0; j < 8; j++) lmn[j] = CUDART_INF_F;

    float hs[KTOP]; int hi[KTOP];
    #pragma unroll
    for (int j = 0; j < KTOP; j++) { hs[j] = -CUDART_INF_F; hi[j] = 0x7fffffff; }
    float thr = -CUDART_INF_F;

    __syncthreads();

    const long tile0 = (long)cta * tpc;
    for (int it = 0; it < tpc; it++) {
        int base = (int)((tile0 + it) * TILE_R);
        if (base >= N) break;
        const bool full = (base + TILE_R <= N);

        // ---- stage tile: coalesced LDG.128, conflict-free swizzled STS.128 ----
        {
            const float4* gsrc = (const float4*)mem + (size_t)base * (DD/4);
            #pragma unroll 8
            for (int j = 0; j < (TILE_R*DD/4)/THREADS; j++) {
                int fi  = t + THREADS*j;
                int row = fi >> 5;
                int c   = fi & 31;
                float4 v = make_float4(0.f, 0.f, 0.f, 0.f);
                if (full || base + row < N) v = gsrc[fi];
                *(float4*)(sA + row*DD + ((c ^ ((row >> 3) & 7)) << 2)) = v;
            }
        }
        __syncthreads();

        // ---- dots: 8 rows x 8 queries per thread, packed f32x2, fused norms ----
        unsigned long long acc[8][4];
        float nrm[8];
        #pragma unroll
        for (int r = 0; r < 8; r++) {
            nrm[r] = 0.f;
            #pragma unroll
            for (int p = 0; p < 4; p++) acc[r][p] = 0ULL;
        }

        #pragma unroll 1
        for (int c = 0; c < 32; c++) {
            const float* qb = sQ + c*4*BQ + b0;
            ulonglong2 q0A = *(const ulonglong2*)(qb);
            ulonglong2 q0B = *(const ulonglong2*)(qb + 4);
            ulonglong2 q1A = *(const ulonglong2*)(qb + BQ);
            ulonglong2 q1B = *(const ulonglong2*)(qb + BQ + 4);
            ulonglong2 q2A = *(const ulonglong2*)(qb + 2*BQ);
            ulonglong2 q2B = *(const ulonglong2*)(qb + 2*BQ + 4);
            ulonglong2 q3A = *(const ulonglong2*)(qb + 3*BQ);
            ulonglong2 q3B = *(const ulonglong2*)(qb + 3*BQ + 4);
            const int co = (c ^ sw) << 2;
            #pragma unroll
            for (int rr = 0; rr < 8; rr++) {
                float4 a = *(const float4*)(sA + (r0 + rr)*DD + co);
                nrm[rr] = fmaf(a.x, a.x, nrm[rr]);
                nrm[rr] = fmaf(a.y, a.y, nrm[rr]);
                nrm[rr] = fmaf(a.z, a.z, nrm[rr]);
                nrm[rr] = fmaf(a.w, a.w, nrm[rr]);
                unsigned long long d;
                d = dup2(a.x);
                fma2(acc[rr][0], d, q0A.x); fma2(acc[rr][1], d, q0A.y);
                fma2(acc[rr][2], d, q0B.x); fma2(acc[rr][3], d, q0B.y);
                d = dup2(a.y);
                fma2(acc[rr][0], d, q1A.x); fma2(acc[rr][1], d, q1A.y);
                fma2(acc[rr][2], d, q1B.x); fma2(acc[rr][3], d, q1B.y);
                d = dup2(a.z);
                fma2(acc[rr][0], d, q2A.x); fma2(acc[rr][1], d, q2A.y);
                fma2(acc[rr][2], d, q2B.x); fma2(acc[rr][3], d, q2B.y);
                d = dup2(a.w);
                fma2(acc[rr][0], d, q3A.x); fma2(acc[rr][1], d, q3A.y);
                fma2(acc[rr][2], d, q3B.x); fma2(acc[rr][3], d, q3B.y);
            }
        }

        // ---- epilogue: exact score, f32x2 stores to sSC[rl][b], min-d2 ----
        #pragma unroll
        for (int rr = 0; rr < 8; rr++) {
            int rl  = r0 + rr;
            int row = base + rl;
            bool valid = full || (row < N);
            if (valid) {
                float mn2  = nrm[rr];
                float inv  = rsqrt_nr(mn2);
                float rec3 = 0.3f * ((float)ts[row] + 1.0f) * inv_ct1;
                float w    = fmaf(0.5f, imp[row], 0.5f);
                #pragma unroll
                for (int p = 0; p < 4; p++) {
                    float lo, hifv; unpack2(acc[rr][p], lo, hifv);
                    int b = b0 + 2*p;
                    float s0 = fmaf(lo  *inv, sCB[b],   rec3) * w;
                    float s1 = fmaf(hifv*inv, sCB[b+1], rec3) * w;
                    *(float2*)(sSC + rl*SCST + b) = make_float2(s0, s1);
                    lmn[2*p  ] = fminf(lmn[2*p  ], fmaf(-2.0f, lo,   mn2));
                    lmn[2*p+1] = fminf(lmn[2*p+1], fmaf(-2.0f, hifv, mn2));
                }
            } else {
                #pragma unroll
                for (int p = 0; p < 4; p++)
                    *(float2*)(sSC + rl*SCST + b0 + 2*p) =
                        make_float2(-CUDART_INF_F, -CUDART_INF_F);
            }
        }
        __syncthreads();

        // ---- scanner: exact top-16 for query t (conflict-free column reads) ----
        if (t < BQ) {
            float th = thr;
            #pragma unroll 4
            for (int e = 0; e < TILE_R; e += 4) {
                float v0 = sSC[(e+0)*SCST + t];
                float v1 = sSC[(e+1)*SCST + t];
                float v2 = sSC[(e+2)*SCST + t];
                float v3 = sSC[(e+3)*SCST + t];
                float mx = fmaxf(fmaxf(v0, v1), fmaxf(v2, v3));
                if (mx > th) {
                    #pragma unroll
                    for (int u = 0; u < 4; u++) {
                        float sc = (u==0)?v0:(u==1)?v1:(u==2)?v2:v3;
                        if (sc > th) {
                            int idx = base + e + u;
                            int pos = KTOP - 1;
                            #pragma unroll
                            for (int s = KTOP - 1; s > 0; s--) {
                                if (sc > hs[s-1]) { hs[s] = hs[s-1]; hi[s] = hi[s-1]; pos = s-1; }
                            }
                            hs[pos] = sc; hi[pos] = idx;
                            th = hs[KTOP-1];
                        }
                    }
                }
            }
            thr = th;
        }
        __syncthreads();
    }

    // ---- reduce lmn across threads (reuse sSC as [query][rowgroup 16]) ----
    #pragma unroll
    for (int j = 0; j < 8; j++) sSC[(b0+j)*16 + rg] = lmn[j];
    __syncthreads();
    if (t < BQ) {
        float m = CUDART_INF_F;
        #pragma unroll
        for (int i = 0; i < 16; i++) m = fminf(m, sSC[t*16 + i]);
        g_minred[cta*BQ + t] = m;
        float* cs = g_cand_s + ((size_t)cta*BQ + t) * KTOP;
        int*   ci = g_cand_i + ((size_t)cta*BQ + t) * KTOP;
        #pragma unroll
        for (int j = 0; j < KTOP; j++) { cs[j] = hs[j]; ci[j] = hi[j]; }
    }
}

// ---------------------------------------------------------------------------
// Kernel 3: merge per-CTA candidates -> exact global top-16 + novelty
// ---------------------------------------------------------------------------
#define MCAND (NCTA*KTOP)
__global__ void __launch_bounds__(256)
k_merge(float* __restrict__ out) {
    __shared__ float cs[MCAND];
    __shared__ int   ci[MCAND];
    __shared__ float rv[256];
    __shared__ int   ri[256];
    __shared__ int   rp[256];

    int q = blockIdx.x;
    int t = threadIdx.x;

    for (int i = t; i < MCAND; i += 256) {
        int c = i >> 4, j = i & (KTOP-1);
        size_t g = ((size_t)c*BQ + q) * KTOP + j;
        cs[i] = g_cand_s[g];
        ci[i] = g_cand_i[g];
    }
    __syncthreads();

    for (int pass = 0; pass < KTOP; pass++) {
        float bv = -CUDART_INF_F; int bi = 0x7fffffff; int bp = 0;
        for (int i = t; i < MCAND; i += 256) {
            float v = cs[i]; int id = ci[i];
            if (v > bv || (v == bv && id < bi)) { bv = v; bi = id; bp = i; }
        }
        rv[t] = bv; ri[t] = bi; rp[t] = bp;
        __syncthreads();
        for (int s = 128; s > 0; s >>= 1) {
            if (t < s) {
                if (rv[t+s] > rv[t] || (rv[t+s] == rv[t] && ri[t+s] < ri[t])) {
                    rv[t] = rv[t+s]; ri[t] = ri[t+s]; rp[t] = rp[t+s];
                }
            }
            __syncthreads();
        }
        if (t == 0) {
            out[q*KTOP + pass]           = rv[0];
            out[BQ*KTOP + q*KTOP + pass] = (float)ri[0];
            cs[rp[0]] = -CUDART_INF_F;
        }
        __syncthreads();
    }

    // novelty
    float m = CUDART_INF_F;
    for (int c = t; c < NCTA; c += 256) m = fminf(m, g_minred[c*BQ + q]);
    rv[t] = m;
    __syncthreads();
    for (int s = 128; s > 0; s >>= 1) {
        if (t < s) rv[t] = fminf(rv[t], rv[t+s]);
        __syncthreads();
    }
    if (t == 0) {
        float qn = g_qn[q];
        float d2 = qn*qn + rv[0];
        float dist = sqrtf(fmaxf(d2, 0.0f));
        out[2*BQ*KTOP + q] = fminf(1.0f, dist * 0.1f);
    }
}

// ---------------------------------------------------------------------------
extern "C" void kernel_launch(void* const* d_in, const int* in_sizes, int n_in,
                              void* d_out, int out_size) {
    const float* query = (const float*)d_in[0];
    const float* mem   = (const float*)d_in[1];
    const float* imp   = (const float*)d_in[2];
    const int*   ts    = (const int*)d_in[3];
    const float* Wq    = (const float*)d_in[4];
    const float* bqv   = (const float*)d_in[5];
    const int*   ct    = (const int*)d_in[6];

    int N = in_sizes[1] / DD;
    float* out = (float*)d_out;

    cudaFuncSetAttribute(k_main, cudaFuncAttributeMaxDynamicSharedMemorySize, SMEM_BYTES);

    k_setup<<<BQ, DD>>>(query, Wq, bqv);
    int tiles = (N + TILE_R - 1) / TILE_R;
    int tpc = (tiles + NCTA - 1) / NCTA;
    k_main<<<NCTA, THREADS, SMEM_BYTES>>>(mem, imp, ts, ct, N, tpc);
    k_merge<<<BQ, 256>>>(out);
}